// round 6
// baseline (speedup 1.0000x reference)
#include <cuda_runtime.h>
#include <cuda_bf16.h>
#include <cstdint>

#define Bsz 16384
#define Fn 26
#define Nrows 100000
#define Dim 64
#define Lk 4
#define NFEAT 27
#define NPAIRS 351
#define OVERIN 415
#define YSTR 416              // padded OVERIN (multiple of 32)
#define DSTR 32               // padded dense-in (13 -> 32)

// ---------------- scratch (device globals) ----------------------------------
__device__ float g_feats[Bsz * NFEAT * Dim];             // (B, 27, 64) fp32
__device__ __nv_bfloat16 g_dsh[Bsz * DSTR],  g_dsl[Bsz * DSTR];
__device__ __nv_bfloat16 g_h1h[Bsz * 512],   g_h1l[Bsz * 512];
__device__ __nv_bfloat16 g_h2h[Bsz * 256],   g_h2l[Bsz * 256];
__device__ __nv_bfloat16 g_yh[Bsz * YSTR],   g_yl[Bsz * YSTR];
// transposed, K-padded weight planes [N][Kpad]
__device__ __nv_bfloat16 g_w0h[512 * DSTR],  g_w0l[512 * DSTR];
__device__ __nv_bfloat16 g_w1h[256 * 512],   g_w1l[256 * 512];
__device__ __nv_bfloat16 g_w2h[64 * 256],    g_w2l[64 * 256];
__device__ __nv_bfloat16 g_t0h[512 * YSTR],  g_t0l[512 * YSTR];
__device__ __nv_bfloat16 g_t1h[256 * 512],   g_t1l[256 * 512];

// ---------------- helpers ----------------------------------------------------
#define MMA_BF16(c, a, b) \
    asm volatile("mma.sync.aligned.m16n8k16.row.col.f32.bf16.bf16.f32 " \
        "{%0,%1,%2,%3}, {%4,%5,%6,%7}, {%8,%9}, {%0,%1,%2,%3};" \
        : "+f"((c)[0]), "+f"((c)[1]), "+f"((c)[2]), "+f"((c)[3]) \
        : "r"((a)[0]), "r"((a)[1]), "r"((a)[2]), "r"((a)[3]), \
          "r"((b)[0]), "r"((b)[1]))

__device__ __forceinline__ void split1(float x, __nv_bfloat16& h, __nv_bfloat16& l)
{
    h = __float2bfloat16(x);
    l = __float2bfloat16(x - __bfloat162float(h));
}

// ---------------- pre-split kernels -----------------------------------------
__global__ void split_dense(const float* __restrict__ in,
                            __nv_bfloat16* __restrict__ oh,
                            __nv_bfloat16* __restrict__ ol)
{
    int idx = blockIdx.x * blockDim.x + threadIdx.x;
    if (idx >= Bsz * DSTR) return;
    int b = idx >> 5, k = idx & 31;
    float v = (k < 13) ? in[b * 13 + k] : 0.f;
    split1(v, oh[idx], ol[idx]);
}

// W (K x N, row-major) -> planes [N][Kpad], zero-padded
__global__ void split_wt(const float* __restrict__ W, int K, int N, int Kpad,
                         __nv_bfloat16* __restrict__ oh,
                         __nv_bfloat16* __restrict__ ol)
{
    int idx = blockIdx.x * blockDim.x + threadIdx.x;
    if (idx >= N * Kpad) return;
    int n = idx / Kpad, k = idx % Kpad;
    float v = (k < K) ? W[(long long)k * N + n] : 0.f;
    split1(v, oh[idx], ol[idx]);
}

// ============ bf16 tensor-core GEMM over pre-split planes ====================
// CTA 128x64, 8 warps (4M x 2N), warp 32x32, K-chunk 32, reg-prefetch pipeline.
#define LDA 40

__global__ __launch_bounds__(256)
void gemm_bf16(const __nv_bfloat16* __restrict__ Ah,
               const __nv_bfloat16* __restrict__ Al,
               const __nv_bfloat16* __restrict__ Bh,
               const __nv_bfloat16* __restrict__ Bl,
               const float* __restrict__ bias, int K, int relu, int outmode,
               float* __restrict__ Cf, int ldcf,
               __nv_bfloat16* __restrict__ Ch, __nv_bfloat16* __restrict__ Cl,
               int ldcb)
{
    __shared__ __align__(16) __nv_bfloat16 As[2][128 * LDA];
    __shared__ __align__(16) __nv_bfloat16 Bs[2][64 * LDA];

    const int tid  = threadIdx.x;
    const int warp = tid >> 5, lane = tid & 31;
    const int wm = warp & 3, wn = warp >> 2;
    const int gid = lane >> 2, tig = lane & 3;
    const int bm = blockIdx.y * 128, bn = blockIdx.x * 64;

    float acc[2][4][4];
    #pragma unroll
    for (int mt = 0; mt < 2; mt++)
        #pragma unroll
        for (int nt = 0; nt < 4; nt++)
            #pragma unroll
            for (int e = 0; e < 4; e++) acc[mt][nt][e] = 0.f;

    const int kIter = K >> 5;           // K is a multiple of 32, zero-padded
    uint4 pa[4], pb[2];

    auto prefetch = [&](int it) {
        const int k0 = it * 32;
        #pragma unroll
        for (int s = 0; s < 4; s++) {
            int idx = tid + s * 256;
            int pl = idx >> 9, rem = idx & 511, r = rem >> 2, kq = rem & 3;
            const __nv_bfloat16* src = (pl ? Al : Ah) +
                (long long)(bm + r) * K + k0 + kq * 8;
            pa[s] = *(const uint4*)src;
        }
        #pragma unroll
        for (int s = 0; s < 2; s++) {
            int idx = tid + s * 256;
            int pl = idx >> 8, rem = idx & 255, n = rem >> 2, kq = rem & 3;
            const __nv_bfloat16* src = (pl ? Bl : Bh) +
                (long long)(bn + n) * K + k0 + kq * 8;
            pb[s] = *(const uint4*)src;
        }
    };

    prefetch(0);
    for (int it = 0; it < kIter; it++) {
        if (it) __syncthreads();        // smem consumed by previous mma block
        #pragma unroll
        for (int s = 0; s < 4; s++) {
            int idx = tid + s * 256;
            int pl = idx >> 9, rem = idx & 511, r = rem >> 2, kq = rem & 3;
            *(uint4*)&As[pl][r * LDA + kq * 8] = pa[s];
        }
        #pragma unroll
        for (int s = 0; s < 2; s++) {
            int idx = tid + s * 256;
            int pl = idx >> 8, rem = idx & 255, n = rem >> 2, kq = rem & 3;
            *(uint4*)&Bs[pl][n * LDA + kq * 8] = pb[s];
        }
        __syncthreads();
        if (it + 1 < kIter) prefetch(it + 1);   // overlap with mma below

        #pragma unroll
        for (int ks = 0; ks < 32; ks += 16) {
            uint32_t ah[2][4], al[2][4], bh[4][2], bl[4][2];
            #pragma unroll
            for (int mt = 0; mt < 2; mt++) {
                int r0 = (wm * 32 + mt * 16 + gid) * LDA + ks + 2 * tig;
                ah[mt][0] = *(const uint32_t*)&As[0][r0];
                ah[mt][1] = *(const uint32_t*)&As[0][r0 + 8 * LDA];
                ah[mt][2] = *(const uint32_t*)&As[0][r0 + 8];
                ah[mt][3] = *(const uint32_t*)&As[0][r0 + 8 * LDA + 8];
                al[mt][0] = *(const uint32_t*)&As[1][r0];
                al[mt][1] = *(const uint32_t*)&As[1][r0 + 8 * LDA];
                al[mt][2] = *(const uint32_t*)&As[1][r0 + 8];
                al[mt][3] = *(const uint32_t*)&As[1][r0 + 8 * LDA + 8];
            }
            #pragma unroll
            for (int nt = 0; nt < 4; nt++) {
                int n0 = (wn * 32 + nt * 8 + gid) * LDA + ks + 2 * tig;
                bh[nt][0] = *(const uint32_t*)&Bs[0][n0];
                bh[nt][1] = *(const uint32_t*)&Bs[0][n0 + 8];
                bl[nt][0] = *(const uint32_t*)&Bs[1][n0];
                bl[nt][1] = *(const uint32_t*)&Bs[1][n0 + 8];
            }
            #pragma unroll
            for (int mt = 0; mt < 2; mt++)
                #pragma unroll
                for (int nt = 0; nt < 4; nt++) {
                    MMA_BF16(acc[mt][nt], ah[mt], bh[nt]);
                    MMA_BF16(acc[mt][nt], ah[mt], bl[nt]);
                    MMA_BF16(acc[mt][nt], al[mt], bh[nt]);
                }
        }
    }

    // ---- epilogue ----
    #pragma unroll
    for (int mt = 0; mt < 2; mt++) {
        int r0 = bm + wm * 32 + mt * 16 + gid;
        #pragma unroll
        for (int nt = 0; nt < 4; nt++) {
            int cc = bn + wn * 32 + nt * 8 + tig * 2;
            float b0 = bias[cc], b1 = bias[cc + 1];
            float v00 = acc[mt][nt][0] + b0, v01 = acc[mt][nt][1] + b1;
            float v10 = acc[mt][nt][2] + b0, v11 = acc[mt][nt][3] + b1;
            if (relu) {
                v00 = fmaxf(v00, 0.f); v01 = fmaxf(v01, 0.f);
                v10 = fmaxf(v10, 0.f); v11 = fmaxf(v11, 0.f);
            }
            if (outmode == 0) {
                *(float2*)&Cf[(long long)r0 * ldcf + cc]       = make_float2(v00, v01);
                *(float2*)&Cf[(long long)(r0 + 8) * ldcf + cc] = make_float2(v10, v11);
            } else {
                __nv_bfloat162 h0, l0, h1v, l1v;
                split1(v00, h0.x, l0.x);  split1(v01, h0.y, l0.y);
                split1(v10, h1v.x, l1v.x); split1(v11, h1v.y, l1v.y);
                *(uint32_t*)&Ch[(long long)r0 * ldcb + cc]       = *(uint32_t*)&h0;
                *(uint32_t*)&Cl[(long long)r0 * ldcb + cc]       = *(uint32_t*)&l0;
                *(uint32_t*)&Ch[(long long)(r0 + 8) * ldcb + cc] = *(uint32_t*)&h1v;
                *(uint32_t*)&Cl[(long long)(r0 + 8) * ldcb + cc] = *(uint32_t*)&l1v;
            }
        }
    }
}

// ---------------- embedding gather + pool: one warp per (f, b) --------------
__global__ __launch_bounds__(256)
void gather_pool(const void* __restrict__ idx_raw,
                 const float* __restrict__ tables,
                 float* __restrict__ feats)
{
    const int gwarp = (blockIdx.x * blockDim.x + threadIdx.x) >> 5;
    const int lane = threadIdx.x & 31;
    if (gwarp >= Fn * Bsz) return;
    const int f = gwarp / Bsz;
    const int b = gwarp % Bsz;

    const long long* p64 = (const long long*)idx_raw;
    long long v0 = p64[0], v1 = p64[123], v2 = p64[4567], v3 = p64[89012];
    const bool is64 = (v0 >= 0 && v0 < Nrows) && (v1 >= 0 && v1 < Nrows) &&
                      (v2 >= 0 && v2 < Nrows) && (v3 >= 0 && v3 < Nrows);
    const int* p32 = (const int*)idx_raw;
    const long long base = (long long)f * Bsz * Lk + (long long)b * Lk;

    float2 acc = make_float2(0.f, 0.f);
    #pragma unroll
    for (int l = 0; l < Lk; l++) {
        long long row = is64 ? p64[base + l] : (long long)p32[base + l];
        const float2* src = (const float2*)(tables + ((long long)f * Nrows + row) * Dim);
        float2 v = src[lane];
        acc.x += v.x; acc.y += v.y;
    }
    float2* dst = (float2*)(feats + (long long)b * (NFEAT * Dim) + (f + 1) * Dim);
    dst[lane] = acc;
}

// ---------------- interaction -> padded bf16 planes -------------------------
__global__ __launch_bounds__(128)
void interact(const float* __restrict__ feats,
              __nv_bfloat16* __restrict__ yh, __nv_bfloat16* __restrict__ yl)
{
    __shared__ float fs[NFEAT * 68];
    const int b = blockIdx.x;
    const int tid = threadIdx.x;
    const float* frow = feats + (long long)b * (NFEAT * Dim);

    for (int i = tid; i < NFEAT * Dim; i += 128)
        fs[(i >> 6) * 68 + (i & 63)] = frow[i];
    __syncthreads();

    __nv_bfloat16* yrh = yh + (long long)b * YSTR;
    __nv_bfloat16* yrl = yl + (long long)b * YSTR;
    for (int i = tid; i < Dim; i += 128) split1(fs[i], yrh[i], yrl[i]);
    if (tid == 0) { yrh[OVERIN] = __float2bfloat16(0.f);
                    yrl[OVERIN] = __float2bfloat16(0.f); }

    for (int p = tid; p < NPAIRS; p += 128) {
        int i = 0, rem = p;
        while (rem >= NFEAT - 1 - i) { rem -= NFEAT - 1 - i; i++; }
        int j = i + 1 + rem;
        const float4* fi = (const float4*)(fs + i * 68);
        const float4* fj = (const float4*)(fs + j * 68);
        float s0 = 0.f, s1 = 0.f;
        #pragma unroll
        for (int k = 0; k < 16; k += 2) {
            float4 a0 = fi[k],     b0v = fj[k];
            float4 a1 = fi[k + 1], b1v = fj[k + 1];
            s0 = fmaf(a0.x, b0v.x, s0); s0 = fmaf(a0.y, b0v.y, s0);
            s0 = fmaf(a0.z, b0v.z, s0); s0 = fmaf(a0.w, b0v.w, s0);
            s1 = fmaf(a1.x, b1v.x, s1); s1 = fmaf(a1.y, b1v.y, s1);
            s1 = fmaf(a1.z, b1v.z, s1); s1 = fmaf(a1.w, b1v.w, s1);
        }
        split1(s0 + s1, yrh[Dim + p], yrl[Dim + p]);
    }
}

// ---------------- final layer over planes: (B,256) @ (256,1) + bias ---------
__global__ __launch_bounds__(256)
void gemv_final(const __nv_bfloat16* __restrict__ Xh,
                const __nv_bfloat16* __restrict__ Xl,
                const float* __restrict__ w,
                const float* __restrict__ bias, float* __restrict__ out)
{
    const int row = (blockIdx.x * blockDim.x + threadIdx.x) >> 5;
    const int lane = threadIdx.x & 31;
    if (row >= Bsz) return;
    uint4 hv = *(const uint4*)(Xh + (long long)row * 256 + lane * 8);
    uint4 lv = *(const uint4*)(Xl + (long long)row * 256 + lane * 8);
    const __nv_bfloat162* hp = (const __nv_bfloat162*)&hv;
    const __nv_bfloat162* lp = (const __nv_bfloat162*)&lv;
    float s = 0.f;
    #pragma unroll
    for (int q = 0; q < 4; q++) {
        float2 h2 = __bfloat1622float2(hp[q]);
        float2 l2 = __bfloat1622float2(lp[q]);
        float w0 = w[lane * 8 + q * 2], w1 = w[lane * 8 + q * 2 + 1];
        s = fmaf(h2.x + l2.x, w0, s);
        s = fmaf(h2.y + l2.y, w1, s);
    }
    #pragma unroll
    for (int o = 16; o; o >>= 1) s += __shfl_down_sync(0xffffffffu, s, o);
    if (lane == 0) out[row] = s + bias[0];
}

// -----------------------------------------------------------------------------
static void* sym_addr(const void* sym)
{
    void* p = nullptr;
    cudaGetSymbolAddress(&p, sym);
    return p;
}

extern "C" void kernel_launch(void* const* d_in, const int* in_sizes, int n_in,
                              void* d_out, int out_size)
{
    (void)in_sizes; (void)n_in; (void)out_size;

    const float* dense   = (const float*)d_in[0];
    const void*  sp_idx  = d_in[1];
    const float* tables  = (const float*)d_in[2];
    const float* botW0   = (const float*)d_in[3];
    const float* botb0   = (const float*)d_in[4];
    const float* botW1   = (const float*)d_in[5];
    const float* botb1   = (const float*)d_in[6];
    const float* botW2   = (const float*)d_in[7];
    const float* botb2   = (const float*)d_in[8];
    const float* topW0   = (const float*)d_in[9];
    const float* topb0   = (const float*)d_in[10];
    const float* topW1   = (const float*)d_in[11];
    const float* topb1   = (const float*)d_in[12];
    const float* topW2   = (const float*)d_in[13];
    const float* topb2   = (const float*)d_in[14];
    float* out = (float*)d_out;

    float* feats = (float*)sym_addr(g_feats);
    __nv_bfloat16* dsh = (__nv_bfloat16*)sym_addr(g_dsh);
    __nv_bfloat16* dsl = (__nv_bfloat16*)sym_addr(g_dsl);
    __nv_bfloat16* h1h = (__nv_bfloat16*)sym_addr(g_h1h);
    __nv_bfloat16* h1l = (__nv_bfloat16*)sym_addr(g_h1l);
    __nv_bfloat16* h2h = (__nv_bfloat16*)sym_addr(g_h2h);
    __nv_bfloat16* h2l = (__nv_bfloat16*)sym_addr(g_h2l);
    __nv_bfloat16* yh  = (__nv_bfloat16*)sym_addr(g_yh);
    __nv_bfloat16* yl  = (__nv_bfloat16*)sym_addr(g_yl);
    __nv_bfloat16* w0h = (__nv_bfloat16*)sym_addr(g_w0h);
    __nv_bfloat16* w0l = (__nv_bfloat16*)sym_addr(g_w0l);
    __nv_bfloat16* w1h = (__nv_bfloat16*)sym_addr(g_w1h);
    __nv_bfloat16* w1l = (__nv_bfloat16*)sym_addr(g_w1l);
    __nv_bfloat16* w2h = (__nv_bfloat16*)sym_addr(g_w2h);
    __nv_bfloat16* w2l = (__nv_bfloat16*)sym_addr(g_w2l);
    __nv_bfloat16* t0h = (__nv_bfloat16*)sym_addr(g_t0h);
    __nv_bfloat16* t0l = (__nv_bfloat16*)sym_addr(g_t0l);
    __nv_bfloat16* t1h = (__nv_bfloat16*)sym_addr(g_t1h);
    __nv_bfloat16* t1l = (__nv_bfloat16*)sym_addr(g_t1l);

    const int MB = Bsz / 128;

    // --- pre-split weights (tiny) + dense input ---
    split_wt<<<(512 * DSTR + 255) / 256, 256>>>(botW0, 13, 512, DSTR, w0h, w0l);
    split_wt<<<(256 * 512 + 255) / 256, 256>>>(botW1, 512, 256, 512, w1h, w1l);
    split_wt<<<(64 * 256 + 255) / 256, 256>>>(botW2, 256, 64, 256, w2h, w2l);
    split_wt<<<(512 * YSTR + 255) / 256, 256>>>(topW0, OVERIN, 512, YSTR, t0h, t0l);
    split_wt<<<(256 * 512 + 255) / 256, 256>>>(topW1, 512, 256, 512, t1h, t1l);
    split_dense<<<(Bsz * DSTR + 255) / 256, 256>>>(dense, dsh, dsl);

    // --- embedding gather + pool (independent) ---
    gather_pool<<<(Fn * Bsz * 32 + 255) / 256, 256>>>(sp_idx, tables, feats);

    // --- bottom MLP ---
    gemm_bf16<<<dim3(8, MB), 256>>>(dsh, dsl, w0h, w0l, botb0, DSTR, 1, 1,
                                    nullptr, 0, h1h, h1l, 512);
    gemm_bf16<<<dim3(4, MB), 256>>>(h1h, h1l, w1h, w1l, botb1, 512, 1, 1,
                                    nullptr, 0, h2h, h2l, 256);
    gemm_bf16<<<dim3(1, MB), 256>>>(h2h, h2l, w2h, w2l, botb2, 256, 1, 0,
                                    feats, NFEAT * Dim, nullptr, nullptr, 0);

    // --- interaction ---
    interact<<<Bsz, 128>>>(feats, yh, yl);

    // --- top MLP ---
    gemm_bf16<<<dim3(8, MB), 256>>>(yh, yl, t0h, t0l, topb0, YSTR, 1, 1,
                                    nullptr, 0, h1h, h1l, 512);
    gemm_bf16<<<dim3(4, MB), 256>>>(h1h, h1l, t1h, t1l, topb1, 512, 1, 1,
                                    nullptr, 0, h2h, h2l, 256);
    gemv_final<<<(Bsz * 32 + 255) / 256, 256>>>(h2h, h2l, topW2, topb2, out);
}

// round 7
// speedup vs baseline: 1.1692x; 1.1692x over previous
#include <cuda_runtime.h>
#include <cuda_fp16.h>
#include <cstdint>

#define Bsz 16384
#define Fn 26
#define Nrows 100000
#define Dim 64
#define Lk 4
#define NFEAT 27
#define NPAIRS 351
#define OVERIN 415
#define YSTR 416
#define DSTR 32

// ---------------- scratch ----------------------------------------------------
__device__ float  g_feats[Bsz * NFEAT * Dim];
__device__ __half g_ds[Bsz * DSTR];
__device__ __half g_h1[Bsz * 512];
__device__ __half g_h2[Bsz * 256];
__device__ __half g_y[Bsz * YSTR];
__device__ __half g_w0h[512 * DSTR],  g_w0l[512 * DSTR];
__device__ __half g_w1h[256 * 512],   g_w1l[256 * 512];
__device__ __half g_w2h[64 * 256],    g_w2l[64 * 256];
__device__ __half g_t0h[512 * YSTR],  g_t0l[512 * YSTR];
__device__ __half g_t1h[256 * 512],   g_t1l[256 * 512];

#define MMA_F16(c, a, b) \
    asm volatile("mma.sync.aligned.m16n8k16.row.col.f32.f16.f16.f32 " \
        "{%0,%1,%2,%3}, {%4,%5,%6,%7}, {%8,%9}, {%0,%1,%2,%3};" \
        : "+f"((c)[0]), "+f"((c)[1]), "+f"((c)[2]), "+f"((c)[3]) \
        : "r"((a)[0]), "r"((a)[1]), "r"((a)[2]), "r"((a)[3]), \
          "r"((b)[0]), "r"((b)[1]))

__device__ __forceinline__ void splitw(float x, __half& h, __half& l)
{
    h = __float2half_rn(x);
    l = __float2half_rn(x - __half2float(h));
}

// ---------------- pre-split kernels ------------------------------------------
__global__ void split_dense(const float* __restrict__ in, __half* __restrict__ o)
{
    int idx = blockIdx.x * blockDim.x + threadIdx.x;
    if (idx >= Bsz * DSTR) return;
    int b = idx >> 5, k = idx & 31;
    o[idx] = __float2half_rn((k < 13) ? in[b * 13 + k] : 0.f);
}

__global__ void split_wt(const float* __restrict__ W, int K, int N, int Kpad,
                         __half* __restrict__ oh, __half* __restrict__ ol)
{
    int idx = blockIdx.x * blockDim.x + threadIdx.x;
    if (idx >= N * Kpad) return;
    int n = idx / Kpad, k = idx % Kpad;
    float v = (k < K) ? W[(long long)k * N + n] : 0.f;
    splitw(v, oh[idx], ol[idx]);
}

// ============ fp16 2-term GEMM: C = act(A @ (Bh+Bl) + bias) ==================
// CTA 128x64, 8 warps (4M x 2N), warp 32x32, K-chunk 32, reg-prefetch.
#define LDA 40

__global__ __launch_bounds__(256)
void gemm_f16(const __half* __restrict__ A,
              const __half* __restrict__ Bh, const __half* __restrict__ Bl,
              const float* __restrict__ bias, int K, int relu, int outmode,
              float* __restrict__ Cf, int ldcf, __half* __restrict__ Ch, int ldch)
{
    __shared__ __align__(16) __half As[128 * LDA];
    __shared__ __align__(16) __half Bs[2][64 * LDA];

    const int tid = threadIdx.x;
    const int warp = tid >> 5, lane = tid & 31;
    const int wm = warp & 3, wn = warp >> 2;
    const int gid = lane >> 2, tig = lane & 3;
    const int bm = blockIdx.y * 128, bn = blockIdx.x * 64;

    float acc[2][4][4] = {};
    const int kIter = K >> 5;
    uint4 pa[2], pb[2];

    auto prefetch = [&](int it) {
        const int k0 = it * 32;
        #pragma unroll
        for (int s = 0; s < 2; s++) {            // A: 128x32 halves = 512 uint4
            int idx = tid + s * 256;
            int r = idx >> 2, kq = idx & 3;
            pa[s] = *(const uint4*)(A + (long long)(bm + r) * K + k0 + kq * 8);
        }
        #pragma unroll
        for (int s = 0; s < 2; s++) {            // B: 2 planes x 64x32
            int idx = tid + s * 256;
            int pl = idx >> 8, rem = idx & 255, n = rem >> 2, kq = rem & 3;
            const __half* src = (pl ? Bl : Bh) + (long long)(bn + n) * K + k0 + kq * 8;
            pb[s] = *(const uint4*)src;
        }
    };

    prefetch(0);
    for (int it = 0; it < kIter; it++) {
        if (it) __syncthreads();
        #pragma unroll
        for (int s = 0; s < 2; s++) {
            int idx = tid + s * 256;
            int r = idx >> 2, kq = idx & 3;
            *(uint4*)&As[r * LDA + kq * 8] = pa[s];
        }
        #pragma unroll
        for (int s = 0; s < 2; s++) {
            int idx = tid + s * 256;
            int pl = idx >> 8, rem = idx & 255, n = rem >> 2, kq = rem & 3;
            *(uint4*)&Bs[pl][n * LDA + kq * 8] = pb[s];
        }
        __syncthreads();
        if (it + 1 < kIter) prefetch(it + 1);

        #pragma unroll
        for (int ks = 0; ks < 32; ks += 16) {
            uint32_t a[2][4], bh[4][2], bl[4][2];
            #pragma unroll
            for (int mt = 0; mt < 2; mt++) {
                int r0 = (wm * 32 + mt * 16 + gid) * LDA + ks + 2 * tig;
                a[mt][0] = *(const uint32_t*)&As[r0];
                a[mt][1] = *(const uint32_t*)&As[r0 + 8 * LDA];
                a[mt][2] = *(const uint32_t*)&As[r0 + 8];
                a[mt][3] = *(const uint32_t*)&As[r0 + 8 * LDA + 8];
            }
            #pragma unroll
            for (int nt = 0; nt < 4; nt++) {
                int n0 = (wn * 32 + nt * 8 + gid) * LDA + ks + 2 * tig;
                bh[nt][0] = *(const uint32_t*)&Bs[0][n0];
                bh[nt][1] = *(const uint32_t*)&Bs[0][n0 + 8];
                bl[nt][0] = *(const uint32_t*)&Bs[1][n0];
                bl[nt][1] = *(const uint32_t*)&Bs[1][n0 + 8];
            }
            #pragma unroll
            for (int mt = 0; mt < 2; mt++)
                #pragma unroll
                for (int nt = 0; nt < 4; nt++) {
                    MMA_F16(acc[mt][nt], a[mt], bh[nt]);
                    MMA_F16(acc[mt][nt], a[mt], bl[nt]);
                }
        }
    }

    #pragma unroll
    for (int mt = 0; mt < 2; mt++) {
        int r0 = bm + wm * 32 + mt * 16 + gid;
        #pragma unroll
        for (int nt = 0; nt < 4; nt++) {
            int cc = bn + wn * 32 + nt * 8 + tig * 2;
            float b0 = bias[cc], b1 = bias[cc + 1];
            float v00 = acc[mt][nt][0] + b0, v01 = acc[mt][nt][1] + b1;
            float v10 = acc[mt][nt][2] + b0, v11 = acc[mt][nt][3] + b1;
            if (relu) {
                v00 = fmaxf(v00, 0.f); v01 = fmaxf(v01, 0.f);
                v10 = fmaxf(v10, 0.f); v11 = fmaxf(v11, 0.f);
            }
            if (outmode == 0) {
                *(float2*)&Cf[(long long)r0 * ldcf + cc]       = make_float2(v00, v01);
                *(float2*)&Cf[(long long)(r0 + 8) * ldcf + cc] = make_float2(v10, v11);
            } else {
                *(__half2*)&Ch[(long long)r0 * ldch + cc]       = __floats2half2_rn(v00, v01);
                *(__half2*)&Ch[(long long)(r0 + 8) * ldch + cc] = __floats2half2_rn(v10, v11);
            }
        }
    }
}

// ---------------- embedding gather + pool ------------------------------------
__global__ __launch_bounds__(256)
void gather_pool(const void* __restrict__ idx_raw,
                 const float* __restrict__ tables, float* __restrict__ feats)
{
    const int gwarp = (blockIdx.x * blockDim.x + threadIdx.x) >> 5;
    const int lane = threadIdx.x & 31;
    if (gwarp >= Fn * Bsz) return;
    const int f = gwarp / Bsz, b = gwarp % Bsz;

    const long long* p64 = (const long long*)idx_raw;
    long long v0 = p64[0], v1 = p64[123], v2 = p64[4567], v3 = p64[89012];
    const bool is64 = (v0 >= 0 && v0 < Nrows) && (v1 >= 0 && v1 < Nrows) &&
                      (v2 >= 0 && v2 < Nrows) && (v3 >= 0 && v3 < Nrows);
    const int* p32 = (const int*)idx_raw;
    const long long base = (long long)f * Bsz * Lk + (long long)b * Lk;

    float2 acc = make_float2(0.f, 0.f);
    #pragma unroll
    for (int l = 0; l < Lk; l++) {
        long long row = is64 ? p64[base + l] : (long long)p32[base + l];
        float2 v = *(const float2*)(tables + ((long long)f * Nrows + row) * Dim + lane * 2);
        acc.x += v.x; acc.y += v.y;
    }
    *(float2*)(feats + (long long)b * (NFEAT * Dim) + (f + 1) * Dim + lane * 2) = acc;
}

// ---------------- interaction -> fp16 yin ------------------------------------
__global__ __launch_bounds__(128)
void interact(const float* __restrict__ feats, __half* __restrict__ y)
{
    __shared__ float fs[NFEAT * 68];
    const int b = blockIdx.x, tid = threadIdx.x;
    const float* frow = feats + (long long)b * (NFEAT * Dim);

    for (int i = tid; i < NFEAT * Dim; i += 128)
        fs[(i >> 6) * 68 + (i & 63)] = frow[i];
    __syncthreads();

    __half* yr = y + (long long)b * YSTR;
    for (int i = tid; i < Dim; i += 128) yr[i] = __float2half_rn(fs[i]);
    if (tid == 0) yr[OVERIN] = __float2half_rn(0.f);

    for (int p = tid; p < NPAIRS; p += 128) {
        int i = 0, rem = p;
        while (rem >= NFEAT - 1 - i) { rem -= NFEAT - 1 - i; i++; }
        int j = i + 1 + rem;
        const float4* fi = (const float4*)(fs + i * 68);
        const float4* fj = (const float4*)(fs + j * 68);
        float s0 = 0.f, s1 = 0.f;
        #pragma unroll
        for (int k = 0; k < 16; k += 2) {
            float4 a0 = fi[k],     b0v = fj[k];
            float4 a1 = fi[k + 1], b1v = fj[k + 1];
            s0 = fmaf(a0.x, b0v.x, s0); s0 = fmaf(a0.y, b0v.y, s0);
            s0 = fmaf(a0.z, b0v.z, s0); s0 = fmaf(a0.w, b0v.w, s0);
            s1 = fmaf(a1.x, b1v.x, s1); s1 = fmaf(a1.y, b1v.y, s1);
            s1 = fmaf(a1.z, b1v.z, s1); s1 = fmaf(a1.w, b1v.w, s1);
        }
        yr[Dim + p] = __float2half_rn(s0 + s1);
    }
}

// ---------------- final layer -------------------------------------------------
__global__ __launch_bounds__(256)
void gemv_final(const __half* __restrict__ X, const float* __restrict__ w,
                const float* __restrict__ bias, float* __restrict__ out)
{
    const int row = (blockIdx.x * blockDim.x + threadIdx.x) >> 5;
    const int lane = threadIdx.x & 31;
    if (row >= Bsz) return;
    uint4 hv = *(const uint4*)(X + (long long)row * 256 + lane * 8);
    const __half2* hp = (const __half2*)&hv;
    float s = 0.f;
    #pragma unroll
    for (int q = 0; q < 4; q++) {
        float2 h2 = __half22float2(hp[q]);
        s = fmaf(h2.x, w[lane * 8 + q * 2], s);
        s = fmaf(h2.y, w[lane * 8 + q * 2 + 1], s);
    }
    #pragma unroll
    for (int o = 16; o; o >>= 1) s += __shfl_down_sync(0xffffffffu, s, o);
    if (lane == 0) out[row] = s + bias[0];
}

// -----------------------------------------------------------------------------
static void* sym_addr(const void* sym)
{
    void* p = nullptr;
    cudaGetSymbolAddress(&p, sym);
    return p;
}

extern "C" void kernel_launch(void* const* d_in, const int* in_sizes, int n_in,
                              void* d_out, int out_size)
{
    (void)in_sizes; (void)n_in; (void)out_size;

    const float* dense  = (const float*)d_in[0];
    const void*  sp_idx = d_in[1];
    const float* tables = (const float*)d_in[2];
    const float* botW0 = (const float*)d_in[3],  *botb0 = (const float*)d_in[4];
    const float* botW1 = (const float*)d_in[5],  *botb1 = (const float*)d_in[6];
    const float* botW2 = (const float*)d_in[7],  *botb2 = (const float*)d_in[8];
    const float* topW0 = (const float*)d_in[9],  *topb0 = (const float*)d_in[10];
    const float* topW1 = (const float*)d_in[11], *topb1 = (const float*)d_in[12];
    const float* topW2 = (const float*)d_in[13], *topb2 = (const float*)d_in[14];
    float* out = (float*)d_out;

    float*  feats = (float*)sym_addr(g_feats);
    __half* ds  = (__half*)sym_addr(g_ds);
    __half* h1  = (__half*)sym_addr(g_h1);
    __half* h2  = (__half*)sym_addr(g_h2);
    __half* y   = (__half*)sym_addr(g_y);
    __half* w0h = (__half*)sym_addr(g_w0h), *w0l = (__half*)sym_addr(g_w0l);
    __half* w1h = (__half*)sym_addr(g_w1h), *w1l = (__half*)sym_addr(g_w1l);
    __half* w2h = (__half*)sym_addr(g_w2h), *w2l = (__half*)sym_addr(g_w2l);
    __half* t0h = (__half*)sym_addr(g_t0h), *t0l = (__half*)sym_addr(g_t0l);
    __half* t1h = (__half*)sym_addr(g_t1h), *t1l = (__half*)sym_addr(g_t1l);

    const int MB = Bsz / 128;

    split_wt<<<(512 * DSTR + 255) / 256, 256>>>(botW0, 13, 512, DSTR, w0h, w0l);
    split_wt<<<(256 * 512 + 255) / 256, 256>>>(botW1, 512, 256, 512, w1h, w1l);
    split_wt<<<(64 * 256 + 255) / 256, 256>>>(botW2, 256, 64, 256, w2h, w2l);
    split_wt<<<(512 * YSTR + 255) / 256, 256>>>(topW0, OVERIN, 512, YSTR, t0h, t0l);
    split_wt<<<(256 * 512 + 255) / 256, 256>>>(topW1, 512, 256, 512, t1h, t1l);
    split_dense<<<(Bsz * DSTR + 255) / 256, 256>>>(dense, ds);

    gather_pool<<<(Fn * Bsz * 32 + 255) / 256, 256>>>(sp_idx, tables, feats);

    gemm_f16<<<dim3(8, MB), 256>>>(ds, w0h, w0l, botb0, DSTR, 1, 1,
                                   nullptr, 0, h1, 512);
    gemm_f16<<<dim3(4, MB), 256>>>(h1, w1h, w1l, botb1, 512, 1, 1,
                                   nullptr, 0, h2, 256);
    gemm_f16<<<dim3(1, MB), 256>>>(h2, w2h, w2l, botb2, 256, 1, 0,
                                   feats, NFEAT * Dim, nullptr, 0);

    interact<<<Bsz, 128>>>(feats, y);

    gemm_f16<<<dim3(8, MB), 256>>>(y, t0h, t0l, topb0, YSTR, 1, 1,
                                   nullptr, 0, h1, 512);
    gemm_f16<<<dim3(4, MB), 256>>>(h1, t1h, t1l, topb1, 512, 1, 1,
                                   nullptr, 0, h2, 256);
    gemv_final<<<(Bsz * 32 + 255) / 256, 256>>>(h2, topW2, topb2, out);
}

// round 8
// speedup vs baseline: 1.3006x; 1.1123x over previous
#include <cuda_runtime.h>
#include <cuda_fp16.h>
#include <cstdint>

#define Bsz 16384
#define Fn 26
#define Nrows 100000
#define Dim 64
#define Lk 4
#define NFEAT 27
#define NPAIRS 351
#define OVERIN 415
#define YSTR 416
#define LDA 40
#define ILD 72

// phase-A grid layout
#define NSPL 1920            // 512(w1)+64(w2)+832(t0)+512(t1)
#define NB0  1024            // b0: 8 x 128 tiles
#define GA_BLK 21120
#define GB_BLK 21120
#define GC_BLK 11008         // 21120+21120+11008 blocks * 8 tasks = 425984

// ---------------- scratch -----------------------------------------------------
__device__ float  g_feats[(size_t)Bsz * NFEAT * Dim];
__device__ __half g_h1[(size_t)Bsz * 512];
__device__ __half g_h2[(size_t)Bsz * 256];
__device__ __half g_y[(size_t)Bsz * YSTR];
__device__ __half g_w1h[256 * 512],  g_w1l[256 * 512];
__device__ __half g_w2h[64 * 256],   g_w2l[64 * 256];
__device__ __half g_t0h[512 * YSTR], g_t0l[512 * YSTR];
__device__ __half g_t1h[256 * 512],  g_t1l[256 * 512];

#define MMA_F16(c, a, b0v, b1v) \
    asm volatile("mma.sync.aligned.m16n8k16.row.col.f32.f16.f16.f32 " \
        "{%0,%1,%2,%3}, {%4,%5,%6,%7}, {%8,%9}, {%0,%1,%2,%3};" \
        : "+f"((c)[0]), "+f"((c)[1]), "+f"((c)[2]), "+f"((c)[3]) \
        : "r"((a)[0]), "r"((a)[1]), "r"((a)[2]), "r"((a)[3]), "r"(b0v), "r"(b1v))

__device__ __forceinline__ void splitw(float x, __half& h, __half& l)
{
    h = __float2half_rn(x);
    l = __float2half_rn(x - __half2float(h));
}

// ---- shared 32-K mma chunk: As[128][LDA], Bp = planes h|l each 64*LDA -------
__device__ __forceinline__ void mma_chunk(const __half* As, const __half* Bp,
    int wm, int wn, int gid, int tig, float acc[2][4][4])
{
    #pragma unroll
    for (int ks = 0; ks < 32; ks += 16) {
        uint32_t a[2][4], bh[4][2], bl[4][2];
        #pragma unroll
        for (int mt = 0; mt < 2; mt++) {
            int r0 = (wm * 32 + mt * 16 + gid) * LDA + ks + 2 * tig;
            a[mt][0] = *(const uint32_t*)&As[r0];
            a[mt][1] = *(const uint32_t*)&As[r0 + 8 * LDA];
            a[mt][2] = *(const uint32_t*)&As[r0 + 8];
            a[mt][3] = *(const uint32_t*)&As[r0 + 8 * LDA + 8];
        }
        #pragma unroll
        for (int nt = 0; nt < 4; nt++) {
            int n0 = (wn * 32 + nt * 8 + gid) * LDA + ks + 2 * tig;
            bh[nt][0] = *(const uint32_t*)&Bp[n0];
            bh[nt][1] = *(const uint32_t*)&Bp[n0 + 8];
            bl[nt][0] = *(const uint32_t*)&Bp[2560 + n0];
            bl[nt][1] = *(const uint32_t*)&Bp[2560 + n0 + 8];
        }
        #pragma unroll
        for (int mt = 0; mt < 2; mt++)
            #pragma unroll
            for (int nt = 0; nt < 4; nt++) {
                MMA_F16(acc[mt][nt], a[mt], bh[nt][0], bh[nt][1]);
                MMA_F16(acc[mt][nt], a[mt], bl[nt][0], bl[nt][1]);
            }
    }
}

__device__ __forceinline__ void gemm_epi(float acc[2][4][4],
    const float* __restrict__ bias, int bm, int bn, int wm, int wn,
    int gid, int tig, int relu, int outmode,
    float* __restrict__ Cf, int ldcf, __half* __restrict__ Ch, int ldch)
{
    #pragma unroll
    for (int mt = 0; mt < 2; mt++) {
        int r0 = bm + wm * 32 + mt * 16 + gid;
        #pragma unroll
        for (int nt = 0; nt < 4; nt++) {
            int cc = bn + wn * 32 + nt * 8 + tig * 2;
            float b0 = bias[cc], b1 = bias[cc + 1];
            float v00 = acc[mt][nt][0] + b0, v01 = acc[mt][nt][1] + b1;
            float v10 = acc[mt][nt][2] + b0, v11 = acc[mt][nt][3] + b1;
            if (relu) {
                v00 = fmaxf(v00, 0.f); v01 = fmaxf(v01, 0.f);
                v10 = fmaxf(v10, 0.f); v11 = fmaxf(v11, 0.f);
            }
            if (outmode == 0) {
                *(float2*)&Cf[(size_t)r0 * ldcf + cc]       = make_float2(v00, v01);
                *(float2*)&Cf[(size_t)(r0 + 8) * ldcf + cc] = make_float2(v10, v11);
            } else {
                *(__half2*)&Ch[(size_t)r0 * ldch + cc]       = __floats2half2_rn(v00, v01);
                *(__half2*)&Ch[(size_t)(r0 + 8) * ldch + cc] = __floats2half2_rn(v10, v11);
            }
        }
    }
}

// ---- generic GEMM core (K mult of 32, reg-prefetch) -------------------------
__device__ void gemm_core(char* smem, const __half* __restrict__ A,
    const __half* __restrict__ Bh, const __half* __restrict__ Bl,
    const float* __restrict__ bias, int K, int bx, int by, int relu,
    int outmode, float* __restrict__ Cf, int ldcf,
    __half* __restrict__ Ch, int ldch)
{
    __half* As = (__half*)smem;
    __half* Bp = (__half*)(smem + 10240);
    const int tid = threadIdx.x, warp = tid >> 5, lane = tid & 31;
    const int wm = warp & 3, wn = warp >> 2;
    const int gid = lane >> 2, tig = lane & 3;
    const int bm = by * 128, bn = bx * 64;

    float acc[2][4][4] = {};
    const int kIter = K >> 5;
    uint4 pa[2], pb[2];

    auto prefetch = [&](int it) {
        const int k0 = it * 32;
        #pragma unroll
        for (int s = 0; s < 2; s++) {
            int idx = tid + s * 256;
            int r = idx >> 2, kq = idx & 3;
            pa[s] = *(const uint4*)(A + (size_t)(bm + r) * K + k0 + kq * 8);
        }
        #pragma unroll
        for (int s = 0; s < 2; s++) {
            int idx = tid + s * 256;
            int pl = idx >> 8, rem = idx & 255, n = rem >> 2, kq = rem & 3;
            const __half* src = (pl ? Bl : Bh) + (size_t)(bn + n) * K + k0 + kq * 8;
            pb[s] = *(const uint4*)src;
        }
    };

    prefetch(0);
    for (int it = 0; it < kIter; it++) {
        if (it) __syncthreads();
        #pragma unroll
        for (int s = 0; s < 2; s++) {
            int idx = tid + s * 256;
            int r = idx >> 2, kq = idx & 3;
            *(uint4*)&As[r * LDA + kq * 8] = pa[s];
        }
        #pragma unroll
        for (int s = 0; s < 2; s++) {
            int idx = tid + s * 256;
            int pl = idx >> 8, rem = idx & 255, n = rem >> 2, kq = rem & 3;
            *(uint4*)&Bp[pl * 2560 + n * LDA + kq * 8] = pb[s];
        }
        __syncthreads();
        if (it + 1 < kIter) prefetch(it + 1);
        mma_chunk(As, Bp, wm, wn, gid, tig, acc);
    }
    gemm_epi(acc, bias, bm, bn, wm, wn, gid, tig, relu, outmode, Cf, ldcf, Ch, ldch);
}

// ---- b0: K=32 (13 real), converts fp32 inputs inline ------------------------
__device__ void b0_role(char* smem, int blk, const float* __restrict__ dense,
    const float* __restrict__ W0, const float* __restrict__ bias,
    __half* __restrict__ h1)
{
    __half* As = (__half*)smem;
    __half* Bp = (__half*)(smem + 10240);
    const int tid = threadIdx.x, warp = tid >> 5, lane = tid & 31;
    const int wm = warp & 3, wn = warp >> 2;
    const int gid = lane >> 2, tig = lane & 3;
    const int by = blk >> 3, bx = blk & 7;
    const int bm = by * 128, bn = bx * 64;

    #pragma unroll
    for (int s = 0; s < 8; s++) {                 // A: 128 x 32 (2048 half2)
        int idx = tid + s * 256;
        int r = idx >> 4, cp = (idx & 15) * 2;
        float x0 = (cp < 13)     ? dense[(size_t)(bm + r) * 13 + cp]     : 0.f;
        float x1 = (cp + 1 < 13) ? dense[(size_t)(bm + r) * 13 + cp + 1] : 0.f;
        *(__half2*)&As[r * LDA + cp] = __floats2half2_rn(x0, x1);
    }
    #pragma unroll
    for (int s = 0; s < 8; s++) {                 // B planes: 64 x 32
        int idx = tid + s * 256;
        int n = idx & 63, k = idx >> 6;
        float v = (k < 13) ? W0[(size_t)k * 512 + bn + n] : 0.f;
        __half h, l; splitw(v, h, l);
        Bp[n * LDA + k] = h;
        Bp[2560 + n * LDA + k] = l;
    }
    __syncthreads();

    float acc[2][4][4] = {};
    mma_chunk(As, Bp, wm, wn, gid, tig, acc);
    gemm_epi(acc, bias, bm, bn, wm, wn, gid, tig, 1, 1, nullptr, 0, h1, 512);
}

// ---- weight split role -------------------------------------------------------
__device__ void split_role(int local, const float* __restrict__ W, int K, int N,
    int Kpad, __half* __restrict__ oh, __half* __restrict__ ol)
{
    int idx = local * 256 + threadIdx.x;
    if (idx >= N * Kpad) return;
    int n = idx / Kpad, k = idx - n * Kpad;
    float v = (k < K) ? W[(size_t)k * N + n] : 0.f;
    splitw(v, oh[idx], ol[idx]);
}

// ---- gather role: 8 warp-tasks per block ------------------------------------
__device__ void gather_role(long long task0, const void* __restrict__ idx_raw,
    const float* __restrict__ tables, float* __restrict__ feats)
{
    const int warp = threadIdx.x >> 5, lane = threadIdx.x & 31;
    const long long t = task0 + warp;
    const int f = (int)(t / Bsz), b = (int)(t % Bsz);

    const long long* p64 = (const long long*)idx_raw;
    long long v0 = p64[0], v1 = p64[123], v2 = p64[4567], v3 = p64[89012];
    const bool is64 = (v0 >= 0 && v0 < Nrows) && (v1 >= 0 && v1 < Nrows) &&
                      (v2 >= 0 && v2 < Nrows) && (v3 >= 0 && v3 < Nrows);
    const int* p32 = (const int*)idx_raw;
    const long long base = (long long)f * Bsz * Lk + (long long)b * Lk;

    float2 acc = make_float2(0.f, 0.f);
    #pragma unroll
    for (int l = 0; l < Lk; l++) {
        long long row = is64 ? p64[base + l] : (long long)p32[base + l];
        float2 v = *(const float2*)(tables + ((long long)f * Nrows + row) * Dim + lane * 2);
        acc.x += v.x; acc.y += v.y;
    }
    *(float2*)(feats + (size_t)b * (NFEAT * Dim) + (f + 1) * Dim + lane * 2) = acc;
}

// ---------------- phase kernels ------------------------------------------------
__global__ __launch_bounds__(256)
void phase_a(const float* dense, const float* W0, const float* b0b, __half* h1,
             const float* W1, __half* w1h, __half* w1l,
             const float* W2, __half* w2h, __half* w2l,
             const float* T0, __half* t0h, __half* t0l,
             const float* T1, __half* t1h, __half* t1l,
             const void* idx, const float* tables, float* feats)
{
    __shared__ char sm[20480];
    int blk = blockIdx.x;
    if (blk < NSPL) {
        if (blk < 512)        split_role(blk,        W1, 512, 256, 512,  w1h, w1l);
        else if (blk < 576)   split_role(blk - 512,  W2, 256, 64,  256,  w2h, w2l);
        else if (blk < 1408)  split_role(blk - 576,  T0, 415, 512, YSTR, t0h, t0l);
        else                  split_role(blk - 1408, T1, 512, 256, 512,  t1h, t1l);
        return;
    }
    blk -= NSPL;
    if (blk < NB0) { b0_role(sm, blk, dense, W0, b0b, h1); return; }
    blk -= NB0;
    gather_role((long long)blk * 8, idx, tables, feats);
}

__global__ __launch_bounds__(256)
void phase_b(const __half* h1, const __half* w1h, const __half* w1l,
             const float* b1b, __half* h2,
             const void* idx, const float* tables, float* feats)
{
    __shared__ char sm[20480];
    int blk = blockIdx.x;
    if (blk < 512) {
        gemm_core(sm, h1, w1h, w1l, b1b, 512, blk & 3, blk >> 2, 1, 1,
                  nullptr, 0, h2, 256);
        return;
    }
    gather_role((long long)GA_BLK * 8 + (long long)(blk - 512) * 8,
                idx, tables, feats);
}

__global__ __launch_bounds__(256)
void phase_c(const __half* h2, const __half* w2h, const __half* w2l,
             const float* b2b, float* feats,
             const void* idx, const float* tables)
{
    __shared__ char sm[20480];
    int blk = blockIdx.x;
    if (blk < 128) {
        gemm_core(sm, h2, w2h, w2l, b2b, 256, 0, blk, 1, 0,
                  feats, NFEAT * Dim, nullptr, 0);
        return;
    }
    gather_role((long long)(GA_BLK + GB_BLK) * 8 + (long long)(blk - 128) * 8,
                idx, tables, feats);
}

__global__ __launch_bounds__(256)
void k_gemm(const __half* A, const __half* Bh, const __half* Bl,
            const float* bias, int K, __half* Ch, int ldch)
{
    __shared__ char sm[20480];
    gemm_core(sm, A, Bh, Bl, bias, K, blockIdx.x, blockIdx.y, 1, 1,
              nullptr, 0, Ch, ldch);
}

// ---------------- tensor-core interaction: 1 warp per sample -----------------
__global__ __launch_bounds__(128)
void interact_mma(const float* __restrict__ feats, __half* __restrict__ y)
{
    __shared__ __half sF[4][2][32 * ILD];      // 36864 B
    const int warp = threadIdx.x >> 5, lane = threadIdx.x & 31;
    const int b = blockIdx.x * 4 + warp;
    const int gid = lane >> 2, tig = lane & 3;
    __half* Fh = &sF[warp][0][0];
    __half* Fl = &sF[warp][1][0];
    const float* fr = feats + (size_t)b * (NFEAT * Dim);

    #pragma unroll
    for (int s = 0; s < 32; s++) {             // 1024 float2 = 32x64
        int idx = lane + s * 32;
        int r = idx >> 5, cp = (idx & 31) * 2;
        float2 v = (r < NFEAT) ? *(const float2*)(fr + r * 64 + cp)
                               : make_float2(0.f, 0.f);
        __half2 h = __floats2half2_rn(v.x, v.y);
        float2 hd = __half22float2(h);
        __half2 l = __floats2half2_rn(v.x - hd.x, v.y - hd.y);
        *(__half2*)&Fh[r * ILD + cp] = h;
        *(__half2*)&Fl[r * ILD + cp] = l;
    }
    __syncwarp();

    float acc[2][4][4] = {};
    #pragma unroll
    for (int ks = 0; ks < 64; ks += 16) {
        uint32_t ah[2][4], al[2][4], bh[4][2], bl[4][2];
        #pragma unroll
        for (int mt = 0; mt < 2; mt++) {
            int r0 = (mt * 16 + gid) * ILD + ks + 2 * tig;
            ah[mt][0] = *(const uint32_t*)&Fh[r0];
            ah[mt][1] = *(const uint32_t*)&Fh[r0 + 8 * ILD];
            ah[mt][2] = *(const uint32_t*)&Fh[r0 + 8];
            ah[mt][3] = *(const uint32_t*)&Fh[r0 + 8 * ILD + 8];
            al[mt][0] = *(const uint32_t*)&Fl[r0];
            al[mt][1] = *(const uint32_t*)&Fl[r0 + 8 * ILD];
            al[mt][2] = *(const uint32_t*)&Fl[r0 + 8];
            al[mt][3] = *(const uint32_t*)&Fl[r0 + 8 * ILD + 8];
        }
        #pragma unroll
        for (int nt = 0; nt < 4; nt++) {
            int n0 = (nt * 8 + gid) * ILD + ks + 2 * tig;
            bh[nt][0] = *(const uint32_t*)&Fh[n0];
            bh[nt][1] = *(const uint32_t*)&Fh[n0 + 8];
            bl[nt][0] = *(const uint32_t*)&Fl[n0];
            bl[nt][1] = *(const uint32_t*)&Fl[n0 + 8];
        }
        #pragma unroll
        for (int mt = 0; mt < 2; mt++)
            #pragma unroll
            for (int nt = 0; nt < 4; nt++) {
                MMA_F16(acc[mt][nt], ah[mt], bh[nt][0], bh[nt][1]);
                MMA_F16(acc[mt][nt], ah[mt], bl[nt][0], bl[nt][1]);
                MMA_F16(acc[mt][nt], al[mt], bh[nt][0], bh[nt][1]);
            }
    }

    __half* yr = y + (size_t)b * YSTR;
    #pragma unroll
    for (int s = 0; s < 2; s++) yr[lane + s * 32] = Fh[lane + s * 32]; // dense row
    if (lane == 0) yr[OVERIN] = __float2half_rn(0.f);

    #pragma unroll
    for (int mt = 0; mt < 2; mt++)
        #pragma unroll
        for (int nt = 0; nt < 4; nt++)
            #pragma unroll
            for (int e = 0; e < 4; e++) {
                int m = mt * 16 + gid + (e >> 1) * 8;
                int n = nt * 8 + tig * 2 + (e & 1);
                if (n > m && n < NFEAT) {
                    int p = m * (2 * NFEAT - m - 1) / 2 + (n - m - 1);
                    yr[Dim + p] = __float2half_rn(acc[mt][nt][e]);
                }
            }
}

// ---------------- final layer ---------------------------------------------------
__global__ __launch_bounds__(256)
void gemv_final(const __half* __restrict__ X, const float* __restrict__ w,
                const float* __restrict__ bias, float* __restrict__ out)
{
    const int row = (blockIdx.x * blockDim.x + threadIdx.x) >> 5;
    const int lane = threadIdx.x & 31;
    if (row >= Bsz) return;
    uint4 hv = *(const uint4*)(X + (size_t)row * 256 + lane * 8);
    const __half2* hp = (const __half2*)&hv;
    float s = 0.f;
    #pragma unroll
    for (int q = 0; q < 4; q++) {
        float2 h2 = __half22float2(hp[q]);
        s = fmaf(h2.x, w[lane * 8 + q * 2], s);
        s = fmaf(h2.y, w[lane * 8 + q * 2 + 1], s);
    }
    #pragma unroll
    for (int o = 16; o; o >>= 1) s += __shfl_down_sync(0xffffffffu, s, o);
    if (lane == 0) out[row] = s + bias[0];
}

// -----------------------------------------------------------------------------
static void* sym_addr(const void* sym)
{
    void* p = nullptr;
    cudaGetSymbolAddress(&p, sym);
    return p;
}

extern "C" void kernel_launch(void* const* d_in, const int* in_sizes, int n_in,
                              void* d_out, int out_size)
{
    (void)in_sizes; (void)n_in; (void)out_size;

    const float* dense  = (const float*)d_in[0];
    const void*  sp_idx = d_in[1];
    const float* tables = (const float*)d_in[2];
    const float* botW0 = (const float*)d_in[3],  *botb0 = (const float*)d_in[4];
    const float* botW1 = (const float*)d_in[5],  *botb1 = (const float*)d_in[6];
    const float* botW2 = (const float*)d_in[7],  *botb2 = (const float*)d_in[8];
    const float* topW0 = (const float*)d_in[9],  *topb0 = (const float*)d_in[10];
    const float* topW1 = (const float*)d_in[11], *topb1 = (const float*)d_in[12];
    const float* topW2 = (const float*)d_in[13], *topb2 = (const float*)d_in[14];
    float* out = (float*)d_out;

    float*  feats = (float*)sym_addr(g_feats);
    __half* h1  = (__half*)sym_addr(g_h1);
    __half* h2  = (__half*)sym_addr(g_h2);
    __half* y   = (__half*)sym_addr(g_y);
    __half* w1h = (__half*)sym_addr(g_w1h), *w1l = (__half*)sym_addr(g_w1l);
    __half* w2h = (__half*)sym_addr(g_w2h), *w2l = (__half*)sym_addr(g_w2l);
    __half* t0h = (__half*)sym_addr(g_t0h), *t0l = (__half*)sym_addr(g_t0l);
    __half* t1h = (__half*)sym_addr(g_t1h), *t1l = (__half*)sym_addr(g_t1l);

    phase_a<<<NSPL + NB0 + GA_BLK, 256>>>(dense, botW0, botb0, h1,
        botW1, w1h, w1l, botW2, w2h, w2l, topW0, t0h, t0l, topW1, t1h, t1l,
        sp_idx, tables, feats);
    phase_b<<<512 + GB_BLK, 256>>>(h1, w1h, w1l, botb1, h2,
                                   sp_idx, tables, feats);
    phase_c<<<128 + GC_BLK, 256>>>(h2, w2h, w2l, botb2, feats,
                                   sp_idx, tables);
    interact_mma<<<Bsz / 4, 128>>>(feats, y);
    k_gemm<<<dim3(8, 128), 256>>>(y, t0h, t0l, topb0, YSTR, h1, 512);
    k_gemm<<<dim3(4, 128), 256>>>(h1, t1h, t1l, topb1, 512, h2, 256);
    gemv_final<<<(Bsz * 32 + 255) / 256, 256>>>(h2, topW2, topb2, out);
}